// round 7
// baseline (speedup 1.0000x reference)
#include <cuda_runtime.h>
#include <cuda_fp16.h>
#include <cstdint>

static constexpr int B_DIM = 8192;   // batch (GEMM M)
static constexpr int N_DIM = 2048;   // nodes / features (GEMM N and K)

// ---------------- scratch (device globals; allocation-free rule) ------------
__device__ __half g_xTh[(size_t)N_DIM * B_DIM];      // x^T  (N, B) fp16
__device__ __half g_lTh[(size_t)N_DIM * B_DIM];      // label^T (N, B) fp16
__device__ __half g_Af[(size_t)B_DIM * N_DIM];       // A fp16 (8192 x 2048)
__device__ __half g_Wf[(size_t)N_DIM * N_DIM];       // W fp16

#define SW64(x) ((x) ^ (((x) >> 3) & 0x30))

// ---------------------------- PTX helpers (sm_80+ only) ---------------------
__device__ __forceinline__ uint32_t smem_u32(const void* p) {
    uint32_t a;
    asm("{ .reg .u64 t; cvta.to.shared.u64 t, %1; cvt.u32.u64 %0, t; }"
        : "=r"(a) : "l"(p));
    return a;
}

__device__ __forceinline__ void cp16(uint32_t saddr, const void* gaddr) {
    asm volatile("cp.async.cg.shared.global [%0], [%1], 16;"
                 :: "r"(saddr), "l"(gaddr) : "memory");
}
#define CP_COMMIT() asm volatile("cp.async.commit_group;" ::: "memory")
#define CP_WAIT(n)  asm volatile("cp.async.wait_group %0;" :: "n"(n) : "memory")

__device__ __forceinline__ void ldsm_x4(uint32_t* r, uint32_t addr) {
    asm volatile("ldmatrix.sync.aligned.m8n8.x4.shared.b16 {%0,%1,%2,%3}, [%4];"
                 : "=r"(r[0]), "=r"(r[1]), "=r"(r[2]), "=r"(r[3]) : "r"(addr));
}

__device__ __forceinline__ void mma_fp16(float* d, const uint32_t* a,
                                         const uint32_t* b) {
    asm volatile(
        "mma.sync.aligned.m16n8k16.row.col.f32.f16.f16.f32 "
        "{%0,%1,%2,%3}, {%4,%5,%6,%7}, {%8,%9}, {%0,%1,%2,%3};"
        : "+f"(d[0]), "+f"(d[1]), "+f"(d[2]), "+f"(d[3])
        : "r"(a[0]), "r"(a[1]), "r"(a[2]), "r"(a[3]), "r"(b[0]), "r"(b[1]));
}

// ---------------------------------------------------------------------------
// Kernel 1: tiled transpose x,label (B,N) fp32 -> (N,B) fp16
// ---------------------------------------------------------------------------
__global__ __launch_bounds__(256) void transpose_kernel(
    const float* __restrict__ x, const float* __restrict__ label)
{
    __shared__ float tile[32][33];   // [node_local][batch_local]
    const float* src = blockIdx.z ? label : x;
    __half* dst      = blockIdx.z ? g_lTh : g_xTh;

    const int node   = blockIdx.x * 32 + threadIdx.x;
    const int batch0 = blockIdx.y * 32;
#pragma unroll
    for (int j = 0; j < 32; j += 8)
        tile[threadIdx.x][threadIdx.y + j] =
            src[(size_t)(batch0 + threadIdx.y + j) * N_DIM + node];
    __syncthreads();

    const int lid = threadIdx.y * 32 + threadIdx.x;   // 0..255
#pragma unroll
    for (int i = lid; i < 512; i += 256) {
        int nr = i >> 4, cp = i & 15;
        __half2 h = __floats2half2_rn(tile[nr][2 * cp], tile[nr][2 * cp + 1]);
        *(__half2*)&dst[(size_t)(blockIdx.x * 32 + nr) * B_DIM
                        + blockIdx.y * 32 + 2 * cp] = h;
    }
}

// ---------------------------------------------------------------------------
// Kernel 2: A[q*8192 + r] = relu( sum_j w0[j]*xT[adj[q][j]][r]
//                                + sum_j w1[j]*lT[adj[q][j]][r] + cb ), fp16.
// ---------------------------------------------------------------------------
__global__ __launch_bounds__(256) void build_A_kernel(
    const int* __restrict__ adj,
    const float* __restrict__ conv_w,
    const float* __restrict__ conv_b)
{
    const int q = blockIdx.y;
    const int r = blockIdx.x * 1024 + threadIdx.x * 4;

    float w[8];
#pragma unroll
    for (int j = 0; j < 8; j++) w[j] = __ldg(&conv_w[j]);
    const float cb = __ldg(&conv_b[0]);

    const int c0 = __ldg(&adj[q * 4 + 0]);
    const int c1 = __ldg(&adj[q * 4 + 1]);
    const int c2 = __ldg(&adj[q * 4 + 2]);
    const int c3 = __ldg(&adj[q * 4 + 3]);

    float4 acc = make_float4(cb, cb, cb, cb);
#define ACC4(buf, col, wj)                                                    \
    {                                                                         \
        uint2 raw = *(const uint2*)&buf[(size_t)(col) * B_DIM + r];           \
        float2 v0 = __half22float2(*(const __half2*)&raw.x);                  \
        float2 v1 = __half22float2(*(const __half2*)&raw.y);                  \
        acc.x = fmaf((wj), v0.x, acc.x);                                      \
        acc.y = fmaf((wj), v0.y, acc.y);                                      \
        acc.z = fmaf((wj), v1.x, acc.z);                                      \
        acc.w = fmaf((wj), v1.y, acc.w);                                      \
    }
    ACC4(g_xTh, c0, w[0]); ACC4(g_xTh, c1, w[1]);
    ACC4(g_xTh, c2, w[2]); ACC4(g_xTh, c3, w[3]);
    ACC4(g_lTh, c0, w[4]); ACC4(g_lTh, c1, w[5]);
    ACC4(g_lTh, c2, w[6]); ACC4(g_lTh, c3, w[7]);
#undef ACC4

    __half2 h01 = __floats2half2_rn(fmaxf(acc.x, 0.f), fmaxf(acc.y, 0.f));
    __half2 h23 = __floats2half2_rn(fmaxf(acc.z, 0.f), fmaxf(acc.w, 0.f));

    __half2* ph = (__half2*)&g_Af[(size_t)q * B_DIM + r];
    ph[0] = h01; ph[1] = h23;
}

// ---------------------------------------------------------------------------
// Kernel 3: convert lin_w to fp16
// ---------------------------------------------------------------------------
__global__ __launch_bounds__(256) void conv_W_kernel(const float* __restrict__ W)
{
    const size_t i = ((size_t)blockIdx.x * 256 + threadIdx.x) * 4;
    float4 v = __ldg((const float4*)(W + i));
    __half2* ph = (__half2*)&g_Wf[i];
    ph[0] = __floats2half2_rn(v.x, v.y);
    ph[1] = __floats2half2_rn(v.z, v.w);
}

// ---------------------------------------------------------------------------
// Kernel 4: mma.sync fp16 GEMM  C = Af @ Wf^T + b
// M=8192, N=2048, K=2048. CTA 128x256, BK=32 (SW64 rows), 4-stage cp.async,
// 8 warps (2m x 4n), warp tile 64x64 (minimizes smem crossbar bytes/MAC).
// ---------------------------------------------------------------------------
static constexpr int BM = 128, BN = 256, BK = 32;
static constexpr int NSTEP = N_DIM / BK;                 // 64
static constexpr int NSTAGE = 4;
static constexpr uint32_t TILE_A  = BM * BK * 2;         // 8192
static constexpr uint32_t TILE_W  = BN * BK * 2;         // 16384
static constexpr uint32_t STAGE_B = TILE_A + TILE_W;     // 24576
static constexpr uint32_t GEMM_SMEM = NSTAGE * STAGE_B;  // 98304

__device__ __forceinline__ void load_stage(uint32_t sbase, int stage,
                                           int m0, int n0, int k0, int tid)
{
    const uint32_t st = sbase + (uint32_t)stage * STAGE_B;
    {   // A: 128 rows x 4 chunks = 512 cp16
#pragma unroll
        for (int i = 0; i < 2; i++) {
            int idx = tid + i * 256;
            int row = idx >> 2, ch = idx & 3;
            uint32_t so = SW64((uint32_t)(row * 64 + ch * 16));
            cp16(st + so, g_Af + (size_t)(m0 + row) * N_DIM + k0 + ch * 8);
        }
    }
    {   // W: 256 rows x 4 chunks = 1024 cp16
#pragma unroll
        for (int i = 0; i < 4; i++) {
            int idx = tid + i * 256;
            int row = idx >> 2, ch = idx & 3;
            uint32_t so = SW64((uint32_t)(row * 64 + ch * 16));
            cp16(st + TILE_A + so,
                 g_Wf + (size_t)(n0 + row) * N_DIM + k0 + ch * 8);
        }
    }
}

__global__ __launch_bounds__(256, 1) void gemm_mma_kernel(
    const float* __restrict__ bias, float* __restrict__ C)
{
    extern __shared__ char smem[];
    const uint32_t sbase = smem_u32(smem);
    const int tid  = threadIdx.x;
    const int wid  = tid >> 5;
    const int lane = tid & 31;
    const int n0 = blockIdx.x * BN;
    const int m0 = blockIdx.y * BM;

    const int warp_row = (wid >> 2) * 64;   // 0 or 64  (m)
    const int warp_col = (wid & 3) * 64;    // 0,64,128,192 (n)

    // hoisted swizzled LDSM offsets (relative to stage base)
    uint32_t offA[2][4], offB[2][4];
#pragma unroll
    for (int ks = 0; ks < 2; ks++) {
        const int ch = ks * 2 + (lane >> 4);
#pragma unroll
        for (int mf = 0; mf < 4; mf++) {
            int row = warp_row + mf * 16 + (lane & 15);
            offA[ks][mf] = SW64((uint32_t)(row * 64 + ch * 16));
        }
#pragma unroll
        for (int g = 0; g < 4; g++) {
            int n = warp_col + g * 16 + (lane & 15);
            offB[ks][g] = TILE_A + SW64((uint32_t)(n * 64 + ch * 16));
        }
    }

    float acc[4][8][4] = {};                // [m frag][n frag][reg]

    load_stage(sbase, 0, m0, n0, 0,      tid); CP_COMMIT();
    load_stage(sbase, 1, m0, n0, BK,     tid); CP_COMMIT();
    load_stage(sbase, 2, m0, n0, 2 * BK, tid); CP_COMMIT();

    for (int it = 0; it < NSTEP; ++it) {
        if (it + 2 < NSTEP)      { CP_WAIT(2); }
        else if (it + 1 < NSTEP) { CP_WAIT(1); }
        else                     { CP_WAIT(0); }
        __syncthreads();

        if (it + 3 < NSTEP) {
            load_stage(sbase, (it + 3) % NSTAGE, m0, n0, (it + 3) * BK, tid);
            CP_COMMIT();
        }

        const uint32_t st = sbase + (uint32_t)(it % NSTAGE) * STAGE_B;
#pragma unroll
        for (int ks = 0; ks < 2; ks++) {
            uint32_t a[4][4], bh[8][2];
#pragma unroll
            for (int mf = 0; mf < 4; mf++)
                ldsm_x4(a[mf], st + offA[ks][mf]);
#pragma unroll
            for (int g = 0; g < 4; g++) {
                uint32_t t[4];
                ldsm_x4(t, st + offB[ks][g]);
                bh[g * 2 + 0][0] = t[0]; bh[g * 2 + 0][1] = t[2];
                bh[g * 2 + 1][0] = t[1]; bh[g * 2 + 1][1] = t[3];
            }
#pragma unroll
            for (int mf = 0; mf < 4; mf++)
#pragma unroll
                for (int nf = 0; nf < 8; nf++)
                    mma_fp16(acc[mf][nf], a[mf], bh[nf]);
        }
        // no trailing barrier: 4 in-flight slots are pairwise distinct;
        // the top-of-loop barrier orders slot reuse.
    }

    // ----- epilogue: add bias, write C -----
    const int r_base = m0 + warp_row + (lane >> 2);
    const int c_base = n0 + warp_col + (lane & 3) * 2;
#pragma unroll
    for (int mf = 0; mf < 4; mf++)
#pragma unroll
        for (int nf = 0; nf < 8; nf++) {
            int r = r_base + mf * 16;
            int c = c_base + nf * 8;
            float b0 = __ldg(&bias[c]), b1 = __ldg(&bias[c + 1]);
            float2 v0 = make_float2(acc[mf][nf][0] + b0, acc[mf][nf][1] + b1);
            float2 v1 = make_float2(acc[mf][nf][2] + b0, acc[mf][nf][3] + b1);
            *(float2*)&C[(size_t)r * N_DIM + c]       = v0;
            *(float2*)&C[(size_t)(r + 8) * N_DIM + c] = v1;
        }
}

// ---------------------------------------------------------------------------
extern "C" void kernel_launch(void* const* d_in, const int* in_sizes, int n_in,
                              void* d_out, int out_size)
{
    const float* x      = (const float*)d_in[0];
    const float* label  = (const float*)d_in[1];
    const int*   adj    = (const int*)  d_in[2];
    const float* conv_w = (const float*)d_in[3];
    const float* conv_b = (const float*)d_in[4];
    const float* lin_w  = (const float*)d_in[5];
    const float* lin_b  = (const float*)d_in[6];
    float* out = (float*)d_out;

    {   // 1) transpose to fp16
        dim3 grid(N_DIM / 32, B_DIM / 32, 2);
        dim3 block(32, 8, 1);
        transpose_kernel<<<grid, block>>>(x, label);
    }
    {   // 2) build A (fp16)
        dim3 grid(B_DIM / (256 * 4), N_DIM, 1);
        build_A_kernel<<<grid, 256>>>(adj, conv_w, conv_b);
    }
    {   // 3) convert W to fp16
        conv_W_kernel<<<(N_DIM * N_DIM / 4) / 256, 256>>>(lin_w);
    }
    {   // 4) tensor-core GEMM via mma.sync (64x64 warp tiles)
        cudaFuncSetAttribute(gemm_mma_kernel,
                             cudaFuncAttributeMaxDynamicSharedMemorySize,
                             GEMM_SMEM);
        dim3 grid(N_DIM / BN, B_DIM / BM, 1);
        gemm_mma_kernel<<<grid, 256, GEMM_SMEM>>>(lin_b, out);
    }
}

// round 8
// speedup vs baseline: 1.0643x; 1.0643x over previous
#include <cuda_runtime.h>
#include <cuda_fp16.h>
#include <cstdint>

static constexpr int B_DIM = 8192;   // batch (GEMM M)
static constexpr int N_DIM = 2048;   // nodes / features (GEMM N and K)

// ---------------- scratch (device globals; allocation-free rule) ------------
__device__ __half g_xTh[(size_t)N_DIM * B_DIM];      // x^T  (N, B) fp16
__device__ __half g_lTh[(size_t)N_DIM * B_DIM];      // label^T (N, B) fp16
__device__ __half g_Af[(size_t)B_DIM * N_DIM];       // A fp16 (8192 x 2048)
__device__ __half g_Wf[(size_t)N_DIM * N_DIM];       // W fp16

#define SW128(x) ((x) ^ (((x) >> 3) & 0x70))

// ---------------------------- PTX helpers (sm_80+ only) ---------------------
__device__ __forceinline__ uint32_t smem_u32(const void* p) {
    uint32_t a;
    asm("{ .reg .u64 t; cvta.to.shared.u64 t, %1; cvt.u32.u64 %0, t; }"
        : "=r"(a) : "l"(p));
    return a;
}

__device__ __forceinline__ void cp16(uint32_t saddr, const void* gaddr) {
    asm volatile("cp.async.cg.shared.global [%0], [%1], 16;"
                 :: "r"(saddr), "l"(gaddr) : "memory");
}
#define CP_COMMIT() asm volatile("cp.async.commit_group;" ::: "memory")
#define CP_WAIT(n)  asm volatile("cp.async.wait_group %0;" :: "n"(n) : "memory")

__device__ __forceinline__ void ldsm_x4(uint32_t* r, uint32_t addr) {
    asm volatile("ldmatrix.sync.aligned.m8n8.x4.shared.b16 {%0,%1,%2,%3}, [%4];"
                 : "=r"(r[0]), "=r"(r[1]), "=r"(r[2]), "=r"(r[3]) : "r"(addr));
}

__device__ __forceinline__ void mma_fp16(float* d, const uint32_t* a,
                                         const uint32_t* b) {
    asm volatile(
        "mma.sync.aligned.m16n8k16.row.col.f32.f16.f16.f32 "
        "{%0,%1,%2,%3}, {%4,%5,%6,%7}, {%8,%9}, {%0,%1,%2,%3};"
        : "+f"(d[0]), "+f"(d[1]), "+f"(d[2]), "+f"(d[3])
        : "r"(a[0]), "r"(a[1]), "r"(a[2]), "r"(a[3]), "r"(b[0]), "r"(b[1]));
}

// ---------------------------------------------------------------------------
// Kernel 1: tiled transpose x,label (B,N) fp32 -> (N,B) fp16
// ---------------------------------------------------------------------------
__global__ __launch_bounds__(256) void transpose_kernel(
    const float* __restrict__ x, const float* __restrict__ label)
{
    __shared__ float tile[32][33];   // [node_local][batch_local]
    const float* src = blockIdx.z ? label : x;
    __half* dst      = blockIdx.z ? g_lTh : g_xTh;

    const int node   = blockIdx.x * 32 + threadIdx.x;
    const int batch0 = blockIdx.y * 32;
#pragma unroll
    for (int j = 0; j < 32; j += 8)
        tile[threadIdx.x][threadIdx.y + j] =
            src[(size_t)(batch0 + threadIdx.y + j) * N_DIM + node];
    __syncthreads();

    const int lid = threadIdx.y * 32 + threadIdx.x;   // 0..255
#pragma unroll
    for (int i = lid; i < 512; i += 256) {
        int nr = i >> 4, cp = i & 15;
        __half2 h = __floats2half2_rn(tile[nr][2 * cp], tile[nr][2 * cp + 1]);
        *(__half2*)&dst[(size_t)(blockIdx.x * 32 + nr) * B_DIM
                        + blockIdx.y * 32 + 2 * cp] = h;
    }
}

// ---------------------------------------------------------------------------
// Kernel 2: A[q*8192 + r] = relu( sum_j w0[j]*xT[adj[q][j]][r]
//                                + sum_j w1[j]*lT[adj[q][j]][r] + cb ), fp16.
// ---------------------------------------------------------------------------
__global__ __launch_bounds__(256) void build_A_kernel(
    const int* __restrict__ adj,
    const float* __restrict__ conv_w,
    const float* __restrict__ conv_b)
{
    const int q = blockIdx.y;
    const int r = blockIdx.x * 1024 + threadIdx.x * 4;

    float w[8];
#pragma unroll
    for (int j = 0; j < 8; j++) w[j] = __ldg(&conv_w[j]);
    const float cb = __ldg(&conv_b[0]);

    const int c0 = __ldg(&adj[q * 4 + 0]);
    const int c1 = __ldg(&adj[q * 4 + 1]);
    const int c2 = __ldg(&adj[q * 4 + 2]);
    const int c3 = __ldg(&adj[q * 4 + 3]);

    float4 acc = make_float4(cb, cb, cb, cb);
#define ACC4(buf, col, wj)                                                    \
    {                                                                         \
        uint2 raw = *(const uint2*)&buf[(size_t)(col) * B_DIM + r];           \
        float2 v0 = __half22float2(*(const __half2*)&raw.x);                  \
        float2 v1 = __half22float2(*(const __half2*)&raw.y);                  \
        acc.x = fmaf((wj), v0.x, acc.x);                                      \
        acc.y = fmaf((wj), v0.y, acc.y);                                      \
        acc.z = fmaf((wj), v1.x, acc.z);                                      \
        acc.w = fmaf((wj), v1.y, acc.w);                                      \
    }
    ACC4(g_xTh, c0, w[0]); ACC4(g_xTh, c1, w[1]);
    ACC4(g_xTh, c2, w[2]); ACC4(g_xTh, c3, w[3]);
    ACC4(g_lTh, c0, w[4]); ACC4(g_lTh, c1, w[5]);
    ACC4(g_lTh, c2, w[6]); ACC4(g_lTh, c3, w[7]);
#undef ACC4

    __half2 h01 = __floats2half2_rn(fmaxf(acc.x, 0.f), fmaxf(acc.y, 0.f));
    __half2 h23 = __floats2half2_rn(fmaxf(acc.z, 0.f), fmaxf(acc.w, 0.f));

    __half2* ph = (__half2*)&g_Af[(size_t)q * B_DIM + r];
    ph[0] = h01; ph[1] = h23;
}

// ---------------------------------------------------------------------------
// Kernel 3: convert lin_w to fp16
// ---------------------------------------------------------------------------
__global__ __launch_bounds__(256) void conv_W_kernel(const float* __restrict__ W)
{
    const size_t i = ((size_t)blockIdx.x * 256 + threadIdx.x) * 4;
    float4 v = __ldg((const float4*)(W + i));
    __half2* ph = (__half2*)&g_Wf[i];
    ph[0] = __floats2half2_rn(v.x, v.y);
    ph[1] = __floats2half2_rn(v.z, v.w);
}

// ---------------------------------------------------------------------------
// Kernel 4: mma.sync fp16 GEMM  C = Af @ Wf^T + b
// M=8192, N=2048, K=2048. CTA 128x256, BK=64 (SW128 rows), 3-stage cp.async,
// 8 warps (2m x 4n), warp tile 64x64, fragment double-buffer for HMMA ILP.
// ---------------------------------------------------------------------------
static constexpr int BM = 128, BN = 256, BK = 64;
static constexpr int NSTEP = N_DIM / BK;                 // 32
static constexpr int NSTAGE = 3;
static constexpr uint32_t TILE_A  = BM * BK * 2;         // 16384
static constexpr uint32_t TILE_W  = BN * BK * 2;         // 32768
static constexpr uint32_t STAGE_B = TILE_A + TILE_W;     // 49152
static constexpr uint32_t GEMM_SMEM = NSTAGE * STAGE_B;  // 147456

__device__ __forceinline__ void load_stage(uint32_t sbase, int stage,
                                           int m0, int n0, int k0, int tid)
{
    const uint32_t st = sbase + (uint32_t)stage * STAGE_B;
#pragma unroll
    for (int i = 0; i < 4; i++) {     // A: 128 rows x 8 chunks = 1024 cp16
        int idx = tid + i * 256;
        int row = idx >> 3, ch = idx & 7;
        uint32_t so = SW128((uint32_t)(row * 128 + ch * 16));
        cp16(st + so, g_Af + (size_t)(m0 + row) * N_DIM + k0 + ch * 8);
    }
#pragma unroll
    for (int i = 0; i < 8; i++) {     // W: 256 rows x 8 chunks = 2048 cp16
        int idx = tid + i * 256;
        int row = idx >> 3, ch = idx & 7;
        uint32_t so = SW128((uint32_t)(row * 128 + ch * 16));
        cp16(st + TILE_A + so, g_Wf + (size_t)(n0 + row) * N_DIM + k0 + ch * 8);
    }
}

struct Frag {
    uint32_t a[4][4];    // 4 m-frags
    uint32_t b[8][2];    // 8 n-frags
};

// ks-step offset trick: within a 128B SW128 row, chunk ch = ks*2 + chsel.
// ks*32 occupies bits [5:6], chsel*16 bit [4], row-xor bits [4:6]; all the
// ks-dependence is a pure XOR:  off(ks) = off(0) ^ (ks << 5).
__device__ __forceinline__ void ld_frags(Frag& f, uint32_t st, int ks,
                                         const uint32_t* offA,
                                         const uint32_t* offB)
{
    const uint32_t kx = (uint32_t)ks << 5;
#pragma unroll
    for (int mf = 0; mf < 4; mf++)
        ldsm_x4(f.a[mf], st + (offA[mf] ^ kx));
#pragma unroll
    for (int g = 0; g < 4; g++) {
        uint32_t t[4];
        ldsm_x4(t, st + (offB[g] ^ kx));
        f.b[g * 2 + 0][0] = t[0]; f.b[g * 2 + 0][1] = t[2];
        f.b[g * 2 + 1][0] = t[1]; f.b[g * 2 + 1][1] = t[3];
    }
}

__global__ __launch_bounds__(256, 1) void gemm_mma_kernel(
    const float* __restrict__ bias, float* __restrict__ C)
{
    extern __shared__ char smem[];
    const uint32_t sbase = smem_u32(smem);
    const int tid  = threadIdx.x;
    const int wid  = tid >> 5;
    const int lane = tid & 31;
    const int n0 = blockIdx.x * BN;
    const int m0 = blockIdx.y * BM;

    const int warp_row = (wid >> 2) * 64;   // 0 or 64  (m)
    const int warp_col = (wid & 3) * 64;    // 0,64,128,192 (n)

    // base swizzled LDSM offsets for ks = 0
    uint32_t offA[4], offB[4];
    {
        const int ch = lane >> 4;            // 0 or 1
#pragma unroll
        for (int mf = 0; mf < 4; mf++) {
            int row = warp_row + mf * 16 + (lane & 15);
            offA[mf] = SW128((uint32_t)(row * 128 + ch * 16));
        }
#pragma unroll
        for (int g = 0; g < 4; g++) {
            int n = warp_col + g * 16 + (lane & 15);
            offB[g] = TILE_A + SW128((uint32_t)(n * 128 + ch * 16));
        }
    }

    float acc[4][8][4] = {};                // [m frag][n frag][reg]

    load_stage(sbase, 0, m0, n0, 0,  tid); CP_COMMIT();
    load_stage(sbase, 1, m0, n0, BK, tid); CP_COMMIT();

    Frag f0, f1;

    for (int it = 0; it < NSTEP; ++it) {
        if (it + 1 < NSTEP) { CP_WAIT(1); } else { CP_WAIT(0); }
        __syncthreads();

        if (it + 2 < NSTEP) {
            load_stage(sbase, (it + 2) % NSTAGE, m0, n0, (it + 2) * BK, tid);
            CP_COMMIT();
        }

        const uint32_t st = sbase + (uint32_t)(it % NSTAGE) * STAGE_B;

        ld_frags(f0, st, 0, offA, offB);
#pragma unroll
        for (int ks = 0; ks < 4; ks++) {
            Frag& cur = (ks & 1) ? f1 : f0;
            Frag& nxt = (ks & 1) ? f0 : f1;
            if (ks < 3) ld_frags(nxt, st, ks + 1, offA, offB);
#pragma unroll
            for (int mf = 0; mf < 4; mf++)
#pragma unroll
                for (int nf = 0; nf < 8; nf++)
                    mma_fp16(acc[mf][nf], cur.a[mf], cur.b[nf]);
        }
        // no trailing barrier: 3 in-flight slots pairwise distinct; the
        // top-of-loop barrier orders slot reuse.
    }

    // ----- epilogue: add bias, write C -----
    const int r_base = m0 + warp_row + (lane >> 2);
    const int c_base = n0 + warp_col + (lane & 3) * 2;
#pragma unroll
    for (int mf = 0; mf < 4; mf++)
#pragma unroll
        for (int nf = 0; nf < 8; nf++) {
            int r = r_base + mf * 16;
            int c = c_base + nf * 8;
            float b0 = __ldg(&bias[c]), b1 = __ldg(&bias[c + 1]);
            float2 v0 = make_float2(acc[mf][nf][0] + b0, acc[mf][nf][1] + b1);
            float2 v1 = make_float2(acc[mf][nf][2] + b0, acc[mf][nf][3] + b1);
            *(float2*)&C[(size_t)r * N_DIM + c]       = v0;
            *(float2*)&C[(size_t)(r + 8) * N_DIM + c] = v1;
        }
}

// ---------------------------------------------------------------------------
extern "C" void kernel_launch(void* const* d_in, const int* in_sizes, int n_in,
                              void* d_out, int out_size)
{
    const float* x      = (const float*)d_in[0];
    const float* label  = (const float*)d_in[1];
    const int*   adj    = (const int*)  d_in[2];
    const float* conv_w = (const float*)d_in[3];
    const float* conv_b = (const float*)d_in[4];
    const float* lin_w  = (const float*)d_in[5];
    const float* lin_b  = (const float*)d_in[6];
    float* out = (float*)d_out;

    {   // 1) transpose to fp16
        dim3 grid(N_DIM / 32, B_DIM / 32, 2);
        dim3 block(32, 8, 1);
        transpose_kernel<<<grid, block>>>(x, label);
    }
    {   // 2) build A (fp16)
        dim3 grid(B_DIM / (256 * 4), N_DIM, 1);
        build_A_kernel<<<grid, 256>>>(adj, conv_w, conv_b);
    }
    {   // 3) convert W to fp16
        conv_W_kernel<<<(N_DIM * N_DIM / 4) / 256, 256>>>(lin_w);
    }
    {   // 4) tensor-core GEMM via mma.sync (64x64 warp tiles, frag dbl-buf)
        cudaFuncSetAttribute(gemm_mma_kernel,
                             cudaFuncAttributeMaxDynamicSharedMemorySize,
                             GEMM_SMEM);
        dim3 grid(N_DIM / BN, B_DIM / BM, 1);
        gemm_mma_kernel<<<grid, 256, GEMM_SMEM>>>(lin_b, out);
    }
}

// round 9
// speedup vs baseline: 1.1861x; 1.1144x over previous
#include <cuda_runtime.h>
#include <cuda_fp16.h>
#include <cstdint>

static constexpr int B_DIM = 8192;   // batch (GEMM M)
static constexpr int N_DIM = 2048;   // nodes / features (GEMM N and K)

// ---------------- scratch (device globals; allocation-free rule) ------------
__device__ __half g_xTh[(size_t)N_DIM * B_DIM];      // x^T  (N, B) fp16
__device__ __half g_lTh[(size_t)N_DIM * B_DIM];      // label^T (N, B) fp16
__device__ __half g_Af[(size_t)B_DIM * N_DIM];       // A fp16 (8192 x 2048)
__device__ __half g_Wf[(size_t)N_DIM * N_DIM];       // W fp16

#define SW128(x) ((x) ^ (((x) >> 3) & 0x70))

// ---------------------------- PTX helpers (sm_80+ only) ---------------------
__device__ __forceinline__ uint32_t smem_u32(const void* p) {
    uint32_t a;
    asm("{ .reg .u64 t; cvta.to.shared.u64 t, %1; cvt.u32.u64 %0, t; }"
        : "=r"(a) : "l"(p));
    return a;
}

__device__ __forceinline__ void cp16(uint32_t saddr, const void* gaddr) {
    asm volatile("cp.async.cg.shared.global [%0], [%1], 16;"
                 :: "r"(saddr), "l"(gaddr) : "memory");
}
#define CP_COMMIT() asm volatile("cp.async.commit_group;" ::: "memory")
#define CP_WAIT(n)  asm volatile("cp.async.wait_group %0;" :: "n"(n) : "memory")

__device__ __forceinline__ void ldsm_x4(uint32_t* r, uint32_t addr) {
    asm volatile("ldmatrix.sync.aligned.m8n8.x4.shared.b16 {%0,%1,%2,%3}, [%4];"
                 : "=r"(r[0]), "=r"(r[1]), "=r"(r[2]), "=r"(r[3]) : "r"(addr));
}

__device__ __forceinline__ void mma_fp16(float* d, const uint32_t* a,
                                         const uint32_t* b) {
    asm volatile(
        "mma.sync.aligned.m16n8k16.row.col.f32.f16.f16.f32 "
        "{%0,%1,%2,%3}, {%4,%5,%6,%7}, {%8,%9}, {%0,%1,%2,%3};"
        : "+f"(d[0]), "+f"(d[1]), "+f"(d[2]), "+f"(d[3])
        : "r"(a[0]), "r"(a[1]), "r"(a[2]), "r"(a[3]), "r"(b[0]), "r"(b[1]));
}

// ---------------------------------------------------------------------------
// Kernel 1: tiled transpose x,label (B,N) fp32 -> (N,B) fp16
// ---------------------------------------------------------------------------
__global__ __launch_bounds__(256) void transpose_kernel(
    const float* __restrict__ x, const float* __restrict__ label)
{
    __shared__ float tile[32][33];   // [node_local][batch_local]
    const float* src = blockIdx.z ? label : x;
    __half* dst      = blockIdx.z ? g_lTh : g_xTh;

    const int node   = blockIdx.x * 32 + threadIdx.x;
    const int batch0 = blockIdx.y * 32;
#pragma unroll
    for (int j = 0; j < 32; j += 8)
        tile[threadIdx.x][threadIdx.y + j] =
            src[(size_t)(batch0 + threadIdx.y + j) * N_DIM + node];
    __syncthreads();

    const int lid = threadIdx.y * 32 + threadIdx.x;   // 0..255
#pragma unroll
    for (int i = lid; i < 512; i += 256) {
        int nr = i >> 4, cp = i & 15;
        __half2 h = __floats2half2_rn(tile[nr][2 * cp], tile[nr][2 * cp + 1]);
        *(__half2*)&dst[(size_t)(blockIdx.x * 32 + nr) * B_DIM
                        + blockIdx.y * 32 + 2 * cp] = h;
    }
}

// ---------------------------------------------------------------------------
// Kernel 2: A[q*8192 + r] = relu( sum_j w0[j]*xT[adj[q][j]][r]
//                                + sum_j w1[j]*lT[adj[q][j]][r] + cb ), fp16.
// ---------------------------------------------------------------------------
__global__ __launch_bounds__(256) void build_A_kernel(
    const int* __restrict__ adj,
    const float* __restrict__ conv_w,
    const float* __restrict__ conv_b)
{
    const int q = blockIdx.y;
    const int r = blockIdx.x * 1024 + threadIdx.x * 4;

    float w[8];
#pragma unroll
    for (int j = 0; j < 8; j++) w[j] = __ldg(&conv_w[j]);
    const float cb = __ldg(&conv_b[0]);

    const int c0 = __ldg(&adj[q * 4 + 0]);
    const int c1 = __ldg(&adj[q * 4 + 1]);
    const int c2 = __ldg(&adj[q * 4 + 2]);
    const int c3 = __ldg(&adj[q * 4 + 3]);

    float4 acc = make_float4(cb, cb, cb, cb);
#define ACC4(buf, col, wj)                                                    \
    {                                                                         \
        uint2 raw = *(const uint2*)&buf[(size_t)(col) * B_DIM + r];           \
        float2 v0 = __half22float2(*(const __half2*)&raw.x);                  \
        float2 v1 = __half22float2(*(const __half2*)&raw.y);                  \
        acc.x = fmaf((wj), v0.x, acc.x);                                      \
        acc.y = fmaf((wj), v0.y, acc.y);                                      \
        acc.z = fmaf((wj), v1.x, acc.z);                                      \
        acc.w = fmaf((wj), v1.y, acc.w);                                      \
    }
    ACC4(g_xTh, c0, w[0]); ACC4(g_xTh, c1, w[1]);
    ACC4(g_xTh, c2, w[2]); ACC4(g_xTh, c3, w[3]);
    ACC4(g_lTh, c0, w[4]); ACC4(g_lTh, c1, w[5]);
    ACC4(g_lTh, c2, w[6]); ACC4(g_lTh, c3, w[7]);
#undef ACC4

    __half2 h01 = __floats2half2_rn(fmaxf(acc.x, 0.f), fmaxf(acc.y, 0.f));
    __half2 h23 = __floats2half2_rn(fmaxf(acc.z, 0.f), fmaxf(acc.w, 0.f));

    __half2* ph = (__half2*)&g_Af[(size_t)q * B_DIM + r];
    ph[0] = h01; ph[1] = h23;
}

// ---------------------------------------------------------------------------
// Kernel 3: convert lin_w to fp16
// ---------------------------------------------------------------------------
__global__ __launch_bounds__(256) void conv_W_kernel(const float* __restrict__ W)
{
    const size_t i = ((size_t)blockIdx.x * 256 + threadIdx.x) * 4;
    float4 v = __ldg((const float4*)(W + i));
    __half2* ph = (__half2*)&g_Wf[i];
    ph[0] = __floats2half2_rn(v.x, v.y);
    ph[1] = __floats2half2_rn(v.z, v.w);
}

// ---------------------------------------------------------------------------
// Kernel 4: mma.sync fp16 GEMM  C = Af @ Wf^T + b
// M=8192, N=2048, K=2048.
// CTA 128x128 with 128 threads (4 warps, 2m x 2n), warp tile 64x64,
// BK=64 (SW128 rows), 3-stage cp.async, 2 CTAs/SM (independent barrier
// domains hide each other's sync bubbles), frag double-buffer for ILP.
// ---------------------------------------------------------------------------
static constexpr int BM = 128, BN = 128, BK = 64;
static constexpr int NSTEP = N_DIM / BK;                 // 32
static constexpr int NSTAGE = 3;
static constexpr uint32_t TILE_A  = BM * BK * 2;         // 16384
static constexpr uint32_t TILE_W  = BN * BK * 2;         // 16384
static constexpr uint32_t STAGE_B = TILE_A + TILE_W;     // 32768
static constexpr uint32_t GEMM_SMEM = NSTAGE * STAGE_B;  // 98304

__device__ __forceinline__ void load_stage(uint32_t sbase, int stage,
                                           int m0, int n0, int k0, int tid)
{
    const uint32_t st = sbase + (uint32_t)stage * STAGE_B;
#pragma unroll
    for (int i = 0; i < 8; i++) {     // A: 128 rows x 8 chunks = 1024 cp16
        int idx = tid + i * 128;
        int row = idx >> 3, ch = idx & 7;
        uint32_t so = SW128((uint32_t)(row * 128 + ch * 16));
        cp16(st + so, g_Af + (size_t)(m0 + row) * N_DIM + k0 + ch * 8);
    }
#pragma unroll
    for (int i = 0; i < 8; i++) {     // W: 128 rows x 8 chunks = 1024 cp16
        int idx = tid + i * 128;
        int row = idx >> 3, ch = idx & 7;
        uint32_t so = SW128((uint32_t)(row * 128 + ch * 16));
        cp16(st + TILE_A + so, g_Wf + (size_t)(n0 + row) * N_DIM + k0 + ch * 8);
    }
}

struct Frag {
    uint32_t a[4][4];    // 4 m-frags
    uint32_t b[8][2];    // 8 n-frags
};

// ks-step offset: chunk index ks*2+chsel lives in byte bits [4:6]; the
// ks-dependence is a pure XOR:  off(ks) = off(0) ^ (ks << 5).
__device__ __forceinline__ void ld_frags(Frag& f, uint32_t st, int ks,
                                         const uint32_t* offA,
                                         const uint32_t* offB)
{
    const uint32_t kx = (uint32_t)ks << 5;
#pragma unroll
    for (int mf = 0; mf < 4; mf++)
        ldsm_x4(f.a[mf], st + (offA[mf] ^ kx));
#pragma unroll
    for (int g = 0; g < 4; g++) {
        uint32_t t[4];
        ldsm_x4(t, st + (offB[g] ^ kx));
        f.b[g * 2 + 0][0] = t[0]; f.b[g * 2 + 0][1] = t[2];
        f.b[g * 2 + 1][0] = t[1]; f.b[g * 2 + 1][1] = t[3];
    }
}

__global__ __launch_bounds__(128, 2) void gemm_mma_kernel(
    const float* __restrict__ bias, float* __restrict__ C)
{
    extern __shared__ char smem[];
    const uint32_t sbase = smem_u32(smem);
    const int tid  = threadIdx.x;
    const int wid  = tid >> 5;
    const int lane = tid & 31;
    const int n0 = blockIdx.x * BN;
    const int m0 = blockIdx.y * BM;

    const int warp_row = (wid >> 1) * 64;   // 0 or 64  (m)
    const int warp_col = (wid & 1) * 64;    // 0 or 64  (n)

    // base swizzled LDSM offsets for ks = 0
    uint32_t offA[4], offB[4];
    {
        const int ch = lane >> 4;            // 0 or 1
#pragma unroll
        for (int mf = 0; mf < 4; mf++) {
            int row = warp_row + mf * 16 + (lane & 15);
            offA[mf] = SW128((uint32_t)(row * 128 + ch * 16));
        }
#pragma unroll
        for (int g = 0; g < 4; g++) {
            int n = warp_col + g * 16 + (lane & 15);
            offB[g] = TILE_A + SW128((uint32_t)(n * 128 + ch * 16));
        }
    }

    float acc[4][8][4] = {};                // [m frag][n frag][reg]

    load_stage(sbase, 0, m0, n0, 0,  tid); CP_COMMIT();
    load_stage(sbase, 1, m0, n0, BK, tid); CP_COMMIT();

    Frag f0, f1;

    for (int it = 0; it < NSTEP; ++it) {
        if (it + 1 < NSTEP) { CP_WAIT(1); } else { CP_WAIT(0); }
        __syncthreads();

        if (it + 2 < NSTEP) {
            load_stage(sbase, (it + 2) % NSTAGE, m0, n0, (it + 2) * BK, tid);
            CP_COMMIT();
        }

        const uint32_t st = sbase + (uint32_t)(it % NSTAGE) * STAGE_B;

        ld_frags(f0, st, 0, offA, offB);
#pragma unroll
        for (int ks = 0; ks < 4; ks++) {
            Frag& cur = (ks & 1) ? f1 : f0;
            Frag& nxt = (ks & 1) ? f0 : f1;
            if (ks < 3) ld_frags(nxt, st, ks + 1, offA, offB);
#pragma unroll
            for (int mf = 0; mf < 4; mf++)
#pragma unroll
                for (int nf = 0; nf < 8; nf++)
                    mma_fp16(acc[mf][nf], cur.a[mf], cur.b[nf]);
        }
        // no trailing barrier: 3 in-flight slots pairwise distinct; the
        // top-of-loop barrier orders slot reuse.
    }

    // ----- epilogue: add bias, write C -----
    const int r_base = m0 + warp_row + (lane >> 2);
    const int c_base = n0 + warp_col + (lane & 3) * 2;
#pragma unroll
    for (int mf = 0; mf < 4; mf++)
#pragma unroll
        for (int nf = 0; nf < 8; nf++) {
            int r = r_base + mf * 16;
            int c = c_base + nf * 8;
            float b0 = __ldg(&bias[c]), b1 = __ldg(&bias[c + 1]);
            float2 v0 = make_float2(acc[mf][nf][0] + b0, acc[mf][nf][1] + b1);
            float2 v1 = make_float2(acc[mf][nf][2] + b0, acc[mf][nf][3] + b1);
            *(float2*)&C[(size_t)r * N_DIM + c]       = v0;
            *(float2*)&C[(size_t)(r + 8) * N_DIM + c] = v1;
        }
}

// ---------------------------------------------------------------------------
extern "C" void kernel_launch(void* const* d_in, const int* in_sizes, int n_in,
                              void* d_out, int out_size)
{
    const float* x      = (const float*)d_in[0];
    const float* label  = (const float*)d_in[1];
    const int*   adj    = (const int*)  d_in[2];
    const float* conv_w = (const float*)d_in[3];
    const float* conv_b = (const float*)d_in[4];
    const float* lin_w  = (const float*)d_in[5];
    const float* lin_b  = (const float*)d_in[6];
    float* out = (float*)d_out;

    {   // 1) transpose to fp16
        dim3 grid(N_DIM / 32, B_DIM / 32, 2);
        dim3 block(32, 8, 1);
        transpose_kernel<<<grid, block>>>(x, label);
    }
    {   // 2) build A (fp16)
        dim3 grid(B_DIM / (256 * 4), N_DIM, 1);
        build_A_kernel<<<grid, 256>>>(adj, conv_w, conv_b);
    }
    {   // 3) convert W to fp16
        conv_W_kernel<<<(N_DIM * N_DIM / 4) / 256, 256>>>(lin_w);
    }
    {   // 4) tensor-core GEMM: 128-thread CTAs, warp 64x64, 2 CTAs/SM
        cudaFuncSetAttribute(gemm_mma_kernel,
                             cudaFuncAttributeMaxDynamicSharedMemorySize,
                             GEMM_SMEM);
        dim3 grid(N_DIM / BN, B_DIM / BM, 1);
        gemm_mma_kernel<<<grid, 128, GEMM_SMEM>>>(lin_b, out);
    }
}

// round 10
// speedup vs baseline: 1.1983x; 1.0102x over previous
#include <cuda_runtime.h>
#include <cuda_fp16.h>
#include <cstdint>

static constexpr int B_DIM = 8192;   // batch (GEMM M)
static constexpr int N_DIM = 2048;   // nodes / features (GEMM N and K)

// ---------------- scratch (device globals; allocation-free rule) ------------
__device__ __half g_xTh[(size_t)N_DIM * B_DIM];      // x^T  (N, B) fp16
__device__ __half g_lTh[(size_t)N_DIM * B_DIM];      // label^T (N, B) fp16
__device__ __half g_Af[(size_t)B_DIM * N_DIM];       // A fp16 (8192 x 2048)
__device__ __half g_Wf[(size_t)N_DIM * N_DIM];       // W fp16

#define SW128(x) ((x) ^ (((x) >> 3) & 0x70))

// ---------------------------- PTX helpers (sm_80+ only) ---------------------
__device__ __forceinline__ uint32_t smem_u32(const void* p) {
    uint32_t a;
    asm("{ .reg .u64 t; cvta.to.shared.u64 t, %1; cvt.u32.u64 %0, t; }"
        : "=r"(a) : "l"(p));
    return a;
}

__device__ __forceinline__ void cp16(uint32_t saddr, const void* gaddr) {
    asm volatile("cp.async.cg.shared.global [%0], [%1], 16;"
                 :: "r"(saddr), "l"(gaddr) : "memory");
}
#define CP_COMMIT() asm volatile("cp.async.commit_group;" ::: "memory")
#define CP_WAIT(n)  asm volatile("cp.async.wait_group %0;" :: "n"(n) : "memory")
#define BAR_SYNC(id, cnt) \
    asm volatile("bar.sync %0, %1;" :: "r"(id), "r"(cnt) : "memory")

__device__ __forceinline__ void ldsm_x4(uint32_t* r, uint32_t addr) {
    asm volatile("ldmatrix.sync.aligned.m8n8.x4.shared.b16 {%0,%1,%2,%3}, [%4];"
                 : "=r"(r[0]), "=r"(r[1]), "=r"(r[2]), "=r"(r[3]) : "r"(addr));
}

__device__ __forceinline__ void mma_fp16(float* d, const uint32_t* a,
                                         const uint32_t* b) {
    asm volatile(
        "mma.sync.aligned.m16n8k16.row.col.f32.f16.f16.f32 "
        "{%0,%1,%2,%3}, {%4,%5,%6,%7}, {%8,%9}, {%0,%1,%2,%3};"
        : "+f"(d[0]), "+f"(d[1]), "+f"(d[2]), "+f"(d[3])
        : "r"(a[0]), "r"(a[1]), "r"(a[2]), "r"(a[3]), "r"(b[0]), "r"(b[1]));
}

// ---------------------------------------------------------------------------
// Kernel 1: tiled transpose x,label (B,N) fp32 -> (N,B) fp16
// ---------------------------------------------------------------------------
__global__ __launch_bounds__(256) void transpose_kernel(
    const float* __restrict__ x, const float* __restrict__ label)
{
    __shared__ float tile[32][33];   // [node_local][batch_local]
    const float* src = blockIdx.z ? label : x;
    __half* dst      = blockIdx.z ? g_lTh : g_xTh;

    const int node   = blockIdx.x * 32 + threadIdx.x;
    const int batch0 = blockIdx.y * 32;
#pragma unroll
    for (int j = 0; j < 32; j += 8)
        tile[threadIdx.x][threadIdx.y + j] =
            src[(size_t)(batch0 + threadIdx.y + j) * N_DIM + node];
    __syncthreads();

    const int lid = threadIdx.y * 32 + threadIdx.x;   // 0..255
#pragma unroll
    for (int i = lid; i < 512; i += 256) {
        int nr = i >> 4, cp = i & 15;
        __half2 h = __floats2half2_rn(tile[nr][2 * cp], tile[nr][2 * cp + 1]);
        *(__half2*)&dst[(size_t)(blockIdx.x * 32 + nr) * B_DIM
                        + blockIdx.y * 32 + 2 * cp] = h;
    }
}

// ---------------------------------------------------------------------------
// Kernel 2: A[q*8192 + r] = relu( sum_j w0[j]*xT[adj[q][j]][r]
//                                + sum_j w1[j]*lT[adj[q][j]][r] + cb ), fp16.
// ---------------------------------------------------------------------------
__global__ __launch_bounds__(256) void build_A_kernel(
    const int* __restrict__ adj,
    const float* __restrict__ conv_w,
    const float* __restrict__ conv_b)
{
    const int q = blockIdx.y;
    const int r = blockIdx.x * 1024 + threadIdx.x * 4;

    float w[8];
#pragma unroll
    for (int j = 0; j < 8; j++) w[j] = __ldg(&conv_w[j]);
    const float cb = __ldg(&conv_b[0]);

    const int c0 = __ldg(&adj[q * 4 + 0]);
    const int c1 = __ldg(&adj[q * 4 + 1]);
    const int c2 = __ldg(&adj[q * 4 + 2]);
    const int c3 = __ldg(&adj[q * 4 + 3]);

    float4 acc = make_float4(cb, cb, cb, cb);
#define ACC4(buf, col, wj)                                                    \
    {                                                                         \
        uint2 raw = *(const uint2*)&buf[(size_t)(col) * B_DIM + r];           \
        float2 v0 = __half22float2(*(const __half2*)&raw.x);                  \
        float2 v1 = __half22float2(*(const __half2*)&raw.y);                  \
        acc.x = fmaf((wj), v0.x, acc.x);                                      \
        acc.y = fmaf((wj), v0.y, acc.y);                                      \
        acc.z = fmaf((wj), v1.x, acc.z);                                      \
        acc.w = fmaf((wj), v1.y, acc.w);                                      \
    }
    ACC4(g_xTh, c0, w[0]); ACC4(g_xTh, c1, w[1]);
    ACC4(g_xTh, c2, w[2]); ACC4(g_xTh, c3, w[3]);
    ACC4(g_lTh, c0, w[4]); ACC4(g_lTh, c1, w[5]);
    ACC4(g_lTh, c2, w[6]); ACC4(g_lTh, c3, w[7]);
#undef ACC4

    __half2 h01 = __floats2half2_rn(fmaxf(acc.x, 0.f), fmaxf(acc.y, 0.f));
    __half2 h23 = __floats2half2_rn(fmaxf(acc.z, 0.f), fmaxf(acc.w, 0.f));

    __half2* ph = (__half2*)&g_Af[(size_t)q * B_DIM + r];
    ph[0] = h01; ph[1] = h23;
}

// ---------------------------------------------------------------------------
// Kernel 3: convert lin_w to fp16
// ---------------------------------------------------------------------------
__global__ __launch_bounds__(256) void conv_W_kernel(const float* __restrict__ W)
{
    const size_t i = ((size_t)blockIdx.x * 256 + threadIdx.x) * 4;
    float4 v = __ldg((const float4*)(W + i));
    __half2* ph = (__half2*)&g_Wf[i];
    ph[0] = __floats2half2_rn(v.x, v.y);
    ph[1] = __floats2half2_rn(v.z, v.w);
}

// ---------------------------------------------------------------------------
// Kernel 4: mma.sync fp16 GEMM  C = Af @ Wf^T + b
// M=8192, N=2048, K=2048. CTA 128x128, 128 threads (4 warps 2m x 2n,
// warp tile 64x64). Each warp OWNS one 64-row tile (A0/A1/W0/W1) and
// cp.asyncs it; producer/consumer sync via 2-warp named barriers — no
// CTA-wide __syncthreads in the mainloop. BK=64 (SW128), 3 stages,
// 2 CTAs/SM, fragment double-buffer.
// ---------------------------------------------------------------------------
static constexpr int BM = 128, BN = 128, BK = 64;
static constexpr int NSTEP = N_DIM / BK;                 // 32
static constexpr int NSTAGE = 3;
static constexpr uint32_t TILE_B  = 64 * BK * 2;         // 8192 per 64-row tile
static constexpr uint32_t STAGE_B = 4 * TILE_B;          // 32768 (A0,A1,W0,W1)
static constexpr uint32_t GEMM_SMEM = NSTAGE * STAGE_B;  // 98304

struct Frag {
    uint32_t a[4][4];    // 4 m-frags
    uint32_t b[8][2];    // 8 n-frags
};

// ks XOR trick: chunk index lives in byte bits [4:6] and does not feed the
// SW128 swizzle mask, so off(ks) = off(0) ^ (ks << 5).
__device__ __forceinline__ void ld_frags(Frag& f, uint32_t st, int ks,
                                         const uint32_t* offA,
                                         const uint32_t* offB)
{
    const uint32_t kx = (uint32_t)ks << 5;
#pragma unroll
    for (int mf = 0; mf < 4; mf++)
        ldsm_x4(f.a[mf], st + (offA[mf] ^ kx));
#pragma unroll
    for (int g = 0; g < 4; g++) {
        uint32_t t[4];
        ldsm_x4(t, st + (offB[g] ^ kx));
        f.b[g * 2 + 0][0] = t[0]; f.b[g * 2 + 0][1] = t[2];
        f.b[g * 2 + 1][0] = t[1]; f.b[g * 2 + 1][1] = t[3];
    }
}

// each warp loads its own 64x128B tile slice for one stage (16 cp16/lane)
__device__ __forceinline__ void load_my_tile(uint32_t st_tile,
                                             const __half* src, int k0,
                                             int lane)
{
#pragma unroll
    for (int i = 0; i < 16; i++) {
        int idx = lane + i * 32;          // 0..511
        int row = idx >> 3, ch = idx & 7;
        uint32_t so = SW128((uint32_t)(row * 128 + ch * 16));
        cp16(st_tile + so, src + (size_t)row * N_DIM + k0 + ch * 8);
    }
}

__global__ __launch_bounds__(128, 2) void gemm_mma_kernel(
    const float* __restrict__ bias, float* __restrict__ C)
{
    extern __shared__ char smem[];
    const uint32_t sbase = smem_u32(smem);
    const int tid  = threadIdx.x;
    const int wid  = tid >> 5;
    const int lane = tid & 31;
    const int n0 = blockIdx.x * BN;
    const int m0 = blockIdx.y * BM;

    const int mg = wid >> 1;                // 0/1 (m half)
    const int ng = wid & 1;                 // 0/1 (n half)
    const int warp_row = mg * 64;
    const int warp_col = ng * 64;

    // tile ownership: w0->A0, w3->A1, w2->W0, w1->W1
    uint32_t my_off;  const __half* my_src;
    if      (wid == 0) { my_off = 0 * TILE_B; my_src = g_Af + (size_t)m0 * N_DIM; }
    else if (wid == 3) { my_off = 1 * TILE_B; my_src = g_Af + (size_t)(m0 + 64) * N_DIM; }
    else if (wid == 2) { my_off = 2 * TILE_B; my_src = g_Wf + (size_t)n0 * N_DIM; }
    else               { my_off = 3 * TILE_B; my_src = g_Wf + (size_t)(n0 + 64) * N_DIM; }

    const int barA = 1 + mg;     // {w00,w01} / {w10,w11}
    const int barW = 3 + ng;     // {w00,w10} / {w01,w11}

    // base swizzled LDSM offsets (ks = 0), local to the owning tile
    uint32_t offA[4], offB[4];
    {
        const int ch = lane >> 4;            // 0 or 1
        const uint32_t aoff = (uint32_t)mg * TILE_B;
        const uint32_t woff = (2u + (uint32_t)ng) * TILE_B;
#pragma unroll
        for (int mf = 0; mf < 4; mf++) {
            int row = mf * 16 + (lane & 15);
            offA[mf] = aoff + SW128((uint32_t)(row * 128 + ch * 16));
        }
#pragma unroll
        for (int g = 0; g < 4; g++) {
            int n = g * 16 + (lane & 15);
            offB[g] = woff + SW128((uint32_t)(n * 128 + ch * 16));
        }
    }

    float acc[4][8][4] = {};                // [m frag][n frag][reg]

    // prologue: each warp loads its own tile for stages 0 and 1
    load_my_tile(sbase + 0 * STAGE_B + my_off, my_src, 0,  lane); CP_COMMIT();
    load_my_tile(sbase + 1 * STAGE_B + my_off, my_src, BK, lane); CP_COMMIT();

    Frag f0, f1;

    for (int it = 0; it < NSTEP; ++it) {
        if (it + 1 < NSTEP) { CP_WAIT(1); } else { CP_WAIT(0); }
        BAR_SYNC(barA, 64);
        BAR_SYNC(barW, 64);

        if (it + 2 < NSTEP) {
            load_my_tile(sbase + (uint32_t)((it + 2) % NSTAGE) * STAGE_B + my_off,
                         my_src, (it + 2) * BK, lane);
            CP_COMMIT();
        }

        const uint32_t st = sbase + (uint32_t)(it % NSTAGE) * STAGE_B;

        ld_frags(f0, st, 0, offA, offB);
#pragma unroll
        for (int ks = 0; ks < 4; ks++) {
            Frag& cur = (ks & 1) ? f1 : f0;
            Frag& nxt = (ks & 1) ? f0 : f1;
            if (ks < 3) ld_frags(nxt, st, ks + 1, offA, offB);
#pragma unroll
            for (int mf = 0; mf < 4; mf++)
#pragma unroll
                for (int nf = 0; nf < 8; nf++)
                    mma_fp16(acc[mf][nf], cur.a[mf], cur.b[nf]);
        }
        // stage reuse safety: writer of slot (it+2)%3 only runs after this
        // barrier; readers of slot it finished before their next barrier.
    }

    // ----- epilogue: add bias, write C (warps disjoint; no sync needed) -----
    const int r_base = m0 + warp_row + (lane >> 2);
    const int c_base = n0 + warp_col + (lane & 3) * 2;
#pragma unroll
    for (int mf = 0; mf < 4; mf++)
#pragma unroll
        for (int nf = 0; nf < 8; nf++) {
            int r = r_base + mf * 16;
            int c = c_base + nf * 8;
            float b0 = __ldg(&bias[c]), b1 = __ldg(&bias[c + 1]);
            float2 v0 = make_float2(acc[mf][nf][0] + b0, acc[mf][nf][1] + b1);
            float2 v1 = make_float2(acc[mf][nf][2] + b0, acc[mf][nf][3] + b1);
            *(float2*)&C[(size_t)r * N_DIM + c]       = v0;
            *(float2*)&C[(size_t)(r + 8) * N_DIM + c] = v1;
        }
}

// ---------------------------------------------------------------------------
extern "C" void kernel_launch(void* const* d_in, const int* in_sizes, int n_in,
                              void* d_out, int out_size)
{
    const float* x      = (const float*)d_in[0];
    const float* label  = (const float*)d_in[1];
    const int*   adj    = (const int*)  d_in[2];
    const float* conv_w = (const float*)d_in[3];
    const float* conv_b = (const float*)d_in[4];
    const float* lin_w  = (const float*)d_in[5];
    const float* lin_b  = (const float*)d_in[6];
    float* out = (float*)d_out;

    {   // 1) transpose to fp16
        dim3 grid(N_DIM / 32, B_DIM / 32, 2);
        dim3 block(32, 8, 1);
        transpose_kernel<<<grid, block>>>(x, label);
    }
    {   // 2) build A (fp16)
        dim3 grid(B_DIM / (256 * 4), N_DIM, 1);
        build_A_kernel<<<grid, 256>>>(adj, conv_w, conv_b);
    }
    {   // 3) convert W to fp16
        conv_W_kernel<<<(N_DIM * N_DIM / 4) / 256, 256>>>(lin_w);
    }
    {   // 4) GEMM: warp-owned tiles + 2-warp named barriers, 2 CTAs/SM
        cudaFuncSetAttribute(gemm_mma_kernel,
                             cudaFuncAttributeMaxDynamicSharedMemorySize,
                             GEMM_SMEM);
        dim3 grid(N_DIM / BN, B_DIM / BM, 1);
        gemm_mma_kernel<<<grid, 128, GEMM_SMEM>>>(lin_b, out);
    }
}

// round 12
// speedup vs baseline: 1.1991x; 1.0007x over previous
#include <cuda_runtime.h>
#include <cuda_fp16.h>
#include <cstdint>

static constexpr int B_DIM = 8192;   // batch (GEMM M)
static constexpr int N_DIM = 2048;   // nodes / features (GEMM N and K)

// ---------------- scratch (device globals; allocation-free rule) ------------
__device__ __half g_xTh[(size_t)N_DIM * B_DIM];      // x^T  (N, B) fp16
__device__ __half g_lTh[(size_t)N_DIM * B_DIM];      // label^T (N, B) fp16
__device__ __half g_Af[(size_t)B_DIM * N_DIM];       // A fp16 (8192 x 2048)
__device__ __half g_Wf[(size_t)N_DIM * N_DIM];       // W fp16

#define SW128(x) ((x) ^ (((x) >> 3) & 0x70))

// ---------------------------- PTX helpers (sm_80+ only) ---------------------
__device__ __forceinline__ uint32_t smem_u32(const void* p) {
    uint32_t a;
    asm("{ .reg .u64 t; cvta.to.shared.u64 t, %1; cvt.u32.u64 %0, t; }"
        : "=r"(a) : "l"(p));
    return a;
}

__device__ __forceinline__ void cp16(uint32_t saddr, const void* gaddr) {
    asm volatile("cp.async.cg.shared.global [%0], [%1], 16;"
                 :: "r"(saddr), "l"(gaddr) : "memory");
}
#define CP_COMMIT() asm volatile("cp.async.commit_group;" ::: "memory")
#define CP_WAIT(n)  asm volatile("cp.async.wait_group %0;" :: "n"(n) : "memory")
#define BAR_SYNC(id, cnt) \
    asm volatile("bar.sync %0, %1;" :: "r"(id), "r"(cnt) : "memory")

__device__ __forceinline__ void ldsm_x4(uint32_t* r, uint32_t addr) {
    asm volatile("ldmatrix.sync.aligned.m8n8.x4.shared.b16 {%0,%1,%2,%3}, [%4];"
                 : "=r"(r[0]), "=r"(r[1]), "=r"(r[2]), "=r"(r[3]) : "r"(addr));
}

__device__ __forceinline__ void mma_fp16(float* d, const uint32_t* a,
                                         const uint32_t* b) {
    asm volatile(
        "mma.sync.aligned.m16n8k16.row.col.f32.f16.f16.f32 "
        "{%0,%1,%2,%3}, {%4,%5,%6,%7}, {%8,%9}, {%0,%1,%2,%3};"
        : "+f"(d[0]), "+f"(d[1]), "+f"(d[2]), "+f"(d[3])
        : "r"(a[0]), "r"(a[1]), "r"(a[2]), "r"(a[3]), "r"(b[0]), "r"(b[1]));
}

// ---------------------------------------------------------------------------
// Kernel 1 (merged prep): z=0/1 -> transpose x/label to fp16; z=2 -> W->fp16.
// ---------------------------------------------------------------------------
__global__ __launch_bounds__(256) void prep_kernel(
    const float* __restrict__ x, const float* __restrict__ label,
    const float* __restrict__ W)
{
    const int tid = threadIdx.x;

    if (blockIdx.z == 2) {
        // W convert: 4096 active blocks handle 2048x2048 floats as uint4.
        const int flat = blockIdx.y * 64 + blockIdx.x;
        if (blockIdx.y >= 64) return;
        const size_t i = ((size_t)flat * 256 + tid) * 4;
        float4 v = __ldg((const float4*)(W + i));
        __half2* ph = (__half2*)&g_Wf[i];
        ph[0] = __floats2half2_rn(v.x, v.y);
        ph[1] = __floats2half2_rn(v.z, v.w);
        return;
    }

    __shared__ float tile[32][33];   // [node_local][batch_local]
    const float* src = blockIdx.z ? label : x;
    __half* dst      = blockIdx.z ? g_lTh : g_xTh;

    const int tx = tid & 31, ty = tid >> 5;        // (32, 8)
    const int node   = blockIdx.x * 32 + tx;
    const int batch0 = blockIdx.y * 32;
#pragma unroll
    for (int j = 0; j < 32; j += 8)
        tile[tx][ty + j] = src[(size_t)(batch0 + ty + j) * N_DIM + node];
    __syncthreads();

#pragma unroll
    for (int i = tid; i < 512; i += 256) {
        int nr = i >> 4, cp = i & 15;
        __half2 h = __floats2half2_rn(tile[nr][2 * cp], tile[nr][2 * cp + 1]);
        *(__half2*)&dst[(size_t)(blockIdx.x * 32 + nr) * B_DIM
                        + blockIdx.y * 32 + 2 * cp] = h;
    }
}

// ---------------------------------------------------------------------------
// Kernel 2: A[q*8192 + r..r+7] = relu( sum_j w0[j]*xT[adj[q][j]][r..]
//                                    + sum_j w1[j]*lT[adj[q][j]][r..] + cb )
// uint4 gathers (8 halves per load), 8 outputs per thread.
// ---------------------------------------------------------------------------
__global__ __launch_bounds__(256) void build_A_kernel(
    const int* __restrict__ adj,
    const float* __restrict__ conv_w,
    const float* __restrict__ conv_b)
{
    const int q = blockIdx.y;
    const int r = (blockIdx.x * 256 + threadIdx.x) * 8;

    float w[8];
#pragma unroll
    for (int j = 0; j < 8; j++) w[j] = __ldg(&conv_w[j]);
    const float cb = __ldg(&conv_b[0]);

    const int c0 = __ldg(&adj[q * 4 + 0]);
    const int c1 = __ldg(&adj[q * 4 + 1]);
    const int c2 = __ldg(&adj[q * 4 + 2]);
    const int c3 = __ldg(&adj[q * 4 + 3]);

    float acc[8];
#pragma unroll
    for (int k = 0; k < 8; k++) acc[k] = cb;

#define ACC8(buf, col, wj)                                                    \
    {                                                                         \
        uint4 raw = *(const uint4*)&buf[(size_t)(col) * B_DIM + r];           \
        const __half2* hp = (const __half2*)&raw;                             \
        _Pragma("unroll")                                                     \
        for (int k = 0; k < 4; k++) {                                         \
            float2 v = __half22float2(hp[k]);                                 \
            acc[2 * k + 0] = fmaf((wj), v.x, acc[2 * k + 0]);                 \
            acc[2 * k + 1] = fmaf((wj), v.y, acc[2 * k + 1]);                 \
        }                                                                     \
    }
    ACC8(g_xTh, c0, w[0]); ACC8(g_xTh, c1, w[1]);
    ACC8(g_xTh, c2, w[2]); ACC8(g_xTh, c3, w[3]);
    ACC8(g_lTh, c0, w[4]); ACC8(g_lTh, c1, w[5]);
    ACC8(g_lTh, c2, w[6]); ACC8(g_lTh, c3, w[7]);
#undef ACC8

    uint4 out;
    __half2* op = (__half2*)&out;
#pragma unroll
    for (int k = 0; k < 4; k++)
        op[k] = __floats2half2_rn(fmaxf(acc[2 * k], 0.f),
                                  fmaxf(acc[2 * k + 1], 0.f));
    *(uint4*)&g_Af[(size_t)q * B_DIM + r] = out;
}

// ---------------------------------------------------------------------------
// Kernel 3: mma.sync fp16 GEMM  C = Af @ Wf^T + b   (unchanged from R10)
// CTA 128x128, 128 threads (4 warps 2m x 2n, warp tile 64x64), BK=64
// (SW128), 3 stages, 2 CTAs/SM, warp-owned tiles + 2-warp named barriers.
// ---------------------------------------------------------------------------
static constexpr int BM = 128, BN = 128, BK = 64;
static constexpr int NSTEP = N_DIM / BK;                 // 32
static constexpr int NSTAGE = 3;
static constexpr uint32_t TILE_B  = 64 * BK * 2;         // 8192 per 64-row tile
static constexpr uint32_t STAGE_B = 4 * TILE_B;          // 32768 (A0,A1,W0,W1)
static constexpr uint32_t GEMM_SMEM = NSTAGE * STAGE_B;  // 98304

struct Frag {
    uint32_t a[4][4];    // 4 m-frags
    uint32_t b[8][2];    // 8 n-frags
};

// ks XOR trick: chunk index lives in byte bits [4:6] and does not feed the
// SW128 swizzle mask, so off(ks) = off(0) ^ (ks << 5).
__device__ __forceinline__ void ld_frags(Frag& f, uint32_t st, int ks,
                                         const uint32_t* offA,
                                         const uint32_t* offB)
{
    const uint32_t kx = (uint32_t)ks << 5;
#pragma unroll
    for (int mf = 0; mf < 4; mf++)
        ldsm_x4(f.a[mf], st + (offA[mf] ^ kx));
#pragma unroll
    for (int g = 0; g < 4; g++) {
        uint32_t t[4];
        ldsm_x4(t, st + (offB[g] ^ kx));
        f.b[g * 2 + 0][0] = t[0]; f.b[g * 2 + 0][1] = t[2];
        f.b[g * 2 + 1][0] = t[1]; f.b[g * 2 + 1][1] = t[3];
    }
}

// each warp loads its own 64x128B tile slice for one stage (16 cp16/lane)
__device__ __forceinline__ void load_my_tile(uint32_t st_tile,
                                             const __half* src, int k0,
                                             int lane)
{
#pragma unroll
    for (int i = 0; i < 16; i++) {
        int idx = lane + i * 32;          // 0..511
        int row = idx >> 3, ch = idx & 7;
        uint32_t so = SW128((uint32_t)(row * 128 + ch * 16));
        cp16(st_tile + so, src + (size_t)row * N_DIM + k0 + ch * 8);
    }
}

__global__ __launch_bounds__(128, 2) void gemm_mma_kernel(
    const float* __restrict__ bias, float* __restrict__ C)
{
    extern __shared__ char smem[];
    const uint32_t sbase = smem_u32(smem);
    const int tid  = threadIdx.x;
    const int wid  = tid >> 5;
    const int lane = tid & 31;
    const int n0 = blockIdx.x * BN;
    const int m0 = blockIdx.y * BM;

    const int mg = wid >> 1;                // 0/1 (m half)
    const int ng = wid & 1;                 // 0/1 (n half)

    // tile ownership: w0->A0, w3->A1, w2->W0, w1->W1
    uint32_t my_off;  const __half* my_src;
    if      (wid == 0) { my_off = 0 * TILE_B; my_src = g_Af + (size_t)m0 * N_DIM; }
    else if (wid == 3) { my_off = 1 * TILE_B; my_src = g_Af + (size_t)(m0 + 64) * N_DIM; }
    else if (wid == 2) { my_off = 2 * TILE_B; my_src = g_Wf + (size_t)n0 * N_DIM; }
    else               { my_off = 3 * TILE_B; my_src = g_Wf + (size_t)(n0 + 64) * N_DIM; }

    const int barA = 1 + mg;     // {w00,w01} / {w10,w11}
    const int barW = 3 + ng;     // {w00,w10} / {w01,w11}

    // base swizzled LDSM offsets (ks = 0), local to the owning tile
    uint32_t offA[4], offB[4];
    {
        const int ch = lane >> 4;            // 0 or 1
        const uint32_t aoff = (uint32_t)mg * TILE_B;
        const uint32_t woff = (2u + (uint32_t)ng) * TILE_B;
#pragma unroll
        for (int mf = 0; mf < 4; mf++) {
            int row = mf * 16 + (lane & 15);
            offA[mf] = aoff + SW128((uint32_t)(row * 128 + ch * 16));
        }
#pragma unroll
        for (int g = 0; g < 4; g++) {
            int n = g * 16 + (lane & 15);
            offB[g] = woff + SW128((uint32_t)(n * 128 + ch * 16));
        }
    }

    float acc[4][8][4] = {};                // [m frag][n frag][reg]

    // prologue: each warp loads its own tile for stages 0 and 1
    load_my_tile(sbase + 0 * STAGE_B + my_off, my_src, 0,  lane); CP_COMMIT();
    load_my_tile(sbase + 1 * STAGE_B + my_off, my_src, BK, lane); CP_COMMIT();

    Frag f0, f1;

    for (int it = 0; it < NSTEP; ++it) {
        if (it + 1 < NSTEP) { CP_WAIT(1); } else { CP_WAIT(0); }
        BAR_SYNC(barA, 64);
        BAR_SYNC(barW, 64);

        if (it + 2 < NSTEP) {
            load_my_tile(sbase + (uint32_t)((it + 2) % NSTAGE) * STAGE_B + my_off,
                         my_src, (it + 2) * BK, lane);
            CP_COMMIT();
        }

        const uint32_t st = sbase + (uint32_t)(it % NSTAGE) * STAGE_B;

        ld_frags(f0, st, 0, offA, offB);
#pragma unroll
        for (int ks = 0; ks < 4; ks++) {
            Frag& cur = (ks & 1) ? f1 : f0;
            Frag& nxt = (ks & 1) ? f0 : f1;
            if (ks < 3) ld_frags(nxt, st, ks + 1, offA, offB);
#pragma unroll
            for (int mf = 0; mf < 4; mf++)
#pragma unroll
                for (int nf = 0; nf < 8; nf++)
                    mma_fp16(acc[mf][nf], cur.a[mf], cur.b[nf]);
        }
    }

    // ----- epilogue: hoisted bias, write C (warps disjoint) -----
    const int r_base = m0 + mg * 64 + (lane >> 2);
    const int c_base = n0 + ng * 64 + (lane & 3) * 2;
    float bb[8][2];
#pragma unroll
    for (int nf = 0; nf < 8; nf++) {
        bb[nf][0] = __ldg(&bias[c_base + nf * 8]);
        bb[nf][1] = __ldg(&bias[c_base + nf * 8 + 1]);
    }
#pragma unroll
    for (int mf = 0; mf < 4; mf++)
#pragma unroll
        for (int nf = 0; nf < 8; nf++) {
            int r = r_base + mf * 16;
            int c = c_base + nf * 8;
            float2 v0 = make_float2(acc[mf][nf][0] + bb[nf][0],
                                    acc[mf][nf][1] + bb[nf][1]);
            float2 v1 = make_float2(acc[mf][nf][2] + bb[nf][0],
                                    acc[mf][nf][3] + bb[nf][1]);
            *(float2*)&C[(size_t)r * N_DIM + c]       = v0;
            *(float2*)&C[(size_t)(r + 8) * N_DIM + c] = v1;
        }
}

// ---------------------------------------------------------------------------
extern "C" void kernel_launch(void* const* d_in, const int* in_sizes, int n_in,
                              void* d_out, int out_size)
{
    const float* x      = (const float*)d_in[0];
    const float* label  = (const float*)d_in[1];
    const int*   adj    = (const int*)  d_in[2];
    const float* conv_w = (const float*)d_in[3];
    const float* conv_b = (const float*)d_in[4];
    const float* lin_w  = (const float*)d_in[5];
    const float* lin_b  = (const float*)d_in[6];
    float* out = (float*)d_out;

    {   // 1) merged prep: transpose x/label to fp16 + convert W to fp16
        dim3 grid(N_DIM / 32, B_DIM / 32, 3);
        prep_kernel<<<grid, 256>>>(x, label, lin_w);
    }
    {   // 2) build A (fp16), 8 outputs/thread
        dim3 grid(B_DIM / (256 * 8), N_DIM, 1);
        build_A_kernel<<<grid, 256>>>(adj, conv_w, conv_b);
    }
    {   // 3) GEMM: warp-owned tiles + 2-warp named barriers, 2 CTAs/SM
        cudaFuncSetAttribute(gemm_mma_kernel,
                             cudaFuncAttributeMaxDynamicSharedMemorySize,
                             GEMM_SMEM);
        dim3 grid(N_DIM / BN, B_DIM / BM, 1);
        gemm_mma_kernel<<<grid, 128, GEMM_SMEM>>>(lin_b, out);
    }
}